// round 9
// baseline (speedup 1.0000x reference)
#include <cuda_runtime.h>

// DFL loss, fused single kernel — single wave (148 SMs x 5 CTAs), 2-way item
// unroll with front-batched loads (8x LDG.128 in flight per warp-iteration).
// pred: [N,64] f32, target: [N,4] f32, weight: [N,1] f32 -> scalar mean.

#define NBLOCKS  740    // 148 SMs * 5 resident CTAs -> exactly one wave
#define NTHREADS 256
#define REG_MAX  16

__device__ float g_partials[NBLOCKS];
__device__ unsigned int g_count = 0;   // re-armed by the last block each launch

// Per-item body: logZ - sel + xlogy terms, hat-weight gather on the FMA pipe.
__device__ __forceinline__ float dfl_body(float4 A, float4 B, float4 C, float4 D,
                                          float t, float wt)
{
    t = fminf(fmaxf(t, 0.0f), (float)(REG_MAX - 1));
    float fl = floorf(t);
    float wr = t - fl;
    float wl = 1.0f - wr;

    const float v[REG_MAX] = {A.x, A.y, A.z, A.w,
                              B.x, B.y, B.z, B.w,
                              C.x, C.y, C.z, C.w,
                              D.x, D.y, D.z, D.w};

    float se  = 0.0f;
    float sel = 0.0f;
    #pragma unroll
    for (int k = 0; k < REG_MAX; k++) {
        se += __expf(v[k]);
        float w = fmaxf(1.0f - fabsf(t - (float)k), 0.0f);
        sel = fmaf(w, v[k], sel);
    }

    float x = __logf(se) - sel;
    if (wl > 0.0f) x = fmaf(wl, __logf(wl), x);
    if (wr > 0.0f) x = fmaf(wr, __logf(wr), x);
    return x * wt;
}

__global__ void __launch_bounds__(NTHREADS, 5)   // ~51-reg budget, 5 CTAs/SM
dfl_fused_kernel(const float* __restrict__ pred,
                 const float* __restrict__ target,
                 const float* __restrict__ weight,
                 float* __restrict__ out,
                 int nitems, float inv)
{
    float acc = 0.0f;
    const int stride = gridDim.x * blockDim.x;   // 189440
    int i = blockIdx.x * blockDim.x + threadIdx.x;

    // 2-way unrolled: front-batch BOTH items' loads (8x LDG.128 + 4 scalars)
    // before either body, doubling outstanding memory per warp.
    for (; i + stride < nitems; i += 2 * stride) {
        const int j = i + stride;
        const float4* p0 = reinterpret_cast<const float4*>(pred) + ((long long)i << 2);
        const float4* p1 = reinterpret_cast<const float4*>(pred) + ((long long)j << 2);
        float4 A0 = p0[0], B0 = p0[1], C0 = p0[2], D0 = p0[3];
        float4 A1 = p1[0], B1 = p1[1], C1 = p1[2], D1 = p1[3];
        float t0 = __ldg(&target[i]);
        float t1 = __ldg(&target[j]);
        float w0 = __ldg(&weight[i >> 2]);
        float w1 = __ldg(&weight[j >> 2]);

        acc += dfl_body(A0, B0, C0, D0, t0, w0);
        acc += dfl_body(A1, B1, C1, D1, t1, w1);
    }
    for (; i < nitems; i += stride) {
        const float4* p0 = reinterpret_cast<const float4*>(pred) + ((long long)i << 2);
        acc += dfl_body(p0[0], p0[1], p0[2], p0[3],
                        __ldg(&target[i]), __ldg(&weight[i >> 2]));
    }

    // ---- deterministic block reduction ----
    #pragma unroll
    for (int o = 16; o > 0; o >>= 1)
        acc += __shfl_xor_sync(0xFFFFFFFFu, acc, o);

    __shared__ float swarp[NTHREADS / 32];
    __shared__ bool  is_last;
    const int lane = threadIdx.x & 31;
    const int wid  = threadIdx.x >> 5;
    if (lane == 0) swarp[wid] = acc;
    __syncthreads();

    if (threadIdx.x == 0) {
        float a = 0.0f;
        #pragma unroll
        for (int k = 0; k < NTHREADS / 32; k++) a += swarp[k];
        g_partials[blockIdx.x] = a;
        __threadfence();
        unsigned int ticket = atomicAdd(&g_count, 1u);
        is_last = (ticket == gridDim.x - 1);
    }
    __syncthreads();

    // ---- last arriving block: final deterministic reduction ----
    if (is_last) {
        float a = 0.0f;
        for (int k = threadIdx.x; k < NBLOCKS; k += NTHREADS)
            a += g_partials[k];
        #pragma unroll
        for (int o = 16; o > 0; o >>= 1)
            a += __shfl_xor_sync(0xFFFFFFFFu, a, o);
        if (lane == 0) swarp[wid] = a;
        __syncthreads();
        if (threadIdx.x == 0) {
            float total = 0.0f;
            #pragma unroll
            for (int k = 0; k < NTHREADS / 32; k++) total += swarp[k];
            out[0]  = total * inv;
            g_count = 0;   // re-arm for next graph replay
        }
    }
}

extern "C" void kernel_launch(void* const* d_in, const int* in_sizes, int n_in,
                              void* d_out, int out_size)
{
    const float* pred   = (const float*)d_in[0];
    const float* target = (const float*)d_in[1];
    const float* weight = (const float*)d_in[2];
    float* out = (float*)d_out;

    const int nitems = in_sizes[1];  // N * 4

    dfl_fused_kernel<<<NBLOCKS, NTHREADS>>>(pred, target, weight, out,
                                            nitems, 1.0f / (float)nitems);
}